// round 1
// baseline (speedup 1.0000x reference)
#include <cuda_runtime.h>
#include <cstdint>

// Problem constants (validated against in_sizes at launch)
#define D 64
#define MAXN 150000   // largest n_total = U + NI = 150000

// Scratch ping-pong feature buffers (no cudaMalloc allowed)
__device__ __align__(16) float g_f0[(size_t)MAXN * D];
__device__ __align__(16) float g_f1[(size_t)MAXN * D];

// sm_90+ vectorized no-return atomic add (4 floats, one L2 RMW op)
__device__ __forceinline__ void red_add_v4(float* addr, float4 v) {
    asm volatile("red.global.add.v4.f32 [%0], {%1,%2,%3,%4};"
                 :: "l"(addr), "f"(v.x), "f"(v.y), "f"(v.z), "f"(v.w)
                 : "memory");
}

// Init: f0 = concat(A,B); out(acc) = feat * 1/3  (layer-0 term, folded scale)
__global__ void init_kernel(const float* __restrict__ A, const float* __restrict__ B,
                            int nA, int n, float* __restrict__ f0,
                            float* __restrict__ outA, float* __restrict__ outB) {
    int idx = blockIdx.x * blockDim.x + threadIdx.x;   // one float4 per thread
    int total = n * (D / 4);
    if (idx >= total) return;
    int row = idx >> 4;
    int c = (idx & 15) * 4;
    const float* src = (row < nA) ? (A + (size_t)row * D) : (B + (size_t)(row - nA) * D);
    float4 v = *(const float4*)(src + c);
    *(float4*)(f0 + (size_t)row * D + c) = v;
    float* dst = (row < nA) ? (outA + (size_t)row * D) : (outB + (size_t)(row - nA) * D);
    const float k = 1.0f / 3.0f;
    float4 s = make_float4(v.x * k, v.y * k, v.z * k, v.w * k);
    *(float4*)(dst + c) = s;
}

// Scatter SpMM: f_out[rows[e]] += vals[e] * f_in[cols[e]]
// 16 threads per edge, each handles one float4 chunk of D=64.
__global__ void scatter_kernel(const int* __restrict__ rows, const int* __restrict__ cols,
                               const float* __restrict__ vals,
                               const float* __restrict__ fin, float* __restrict__ fout,
                               int nnz) {
    long long t = (long long)blockIdx.x * blockDim.x + threadIdx.x;
    int e = (int)(t >> 4);
    if (e >= nnz) return;
    int c = ((int)t & 15) * 4;
    int r  = rows[e];
    int cl = cols[e];
    float v = vals[e];
    float4 x = *(const float4*)(fin + (size_t)cl * D + c);
    x.x *= v; x.y *= v; x.z *= v; x.w *= v;
    red_add_v4(fout + (size_t)r * D + c, x);
}

// Per-row L2 normalize f, then out += (1/3) * f / max(||f||, 1e-12).
// One warp per row; each lane owns a float2 (64 floats total).
__global__ void norm_acc_kernel(const float* __restrict__ f, int nA, int n,
                                float* __restrict__ outA, float* __restrict__ outB) {
    int warp = (int)((blockIdx.x * blockDim.x + threadIdx.x) >> 5);
    int lane = threadIdx.x & 31;
    if (warp >= n) return;
    const float2* fr = (const float2*)(f + (size_t)warp * D);
    float2 a = fr[lane];
    float s = a.x * a.x + a.y * a.y;
    #pragma unroll
    for (int o = 16; o; o >>= 1) s += __shfl_xor_sync(0xffffffffu, s, o);
    float nrm = sqrtf(s);
    float scale = (1.0f / 3.0f) / fmaxf(nrm, 1e-12f);
    float* dst = (warp < nA) ? (outA + (size_t)warp * D) : (outB + (size_t)(warp - nA) * D);
    float2* d2 = (float2*)dst;
    float2 o2 = d2[lane];
    o2.x += a.x * scale;
    o2.y += a.y * scale;
    d2[lane] = o2;
}

static void run_prop(const int* rows, const int* cols, const float* vals, int nnz,
                     const float* A, const float* B, int nA, int nB,
                     float* outA, float* outB, float* f0, float* f1) {
    int n = nA + nB;
    int total4 = n * (D / 4);
    init_kernel<<<(total4 + 255) / 256, 256>>>(A, B, nA, n, f0, outA, outB);
    for (int L = 0; L < 2; L++) {
        cudaMemsetAsync(f1, 0, (size_t)n * D * sizeof(float), 0);
        long long tt = (long long)nnz * 16;
        scatter_kernel<<<(unsigned)((tt + 255) / 256), 256>>>(rows, cols, vals, f0, f1, nnz);
        norm_acc_kernel<<<(n + 7) / 8, 256>>>(f1, nA, n, outA, outB);
        float* tmp = f0; f0 = f1; f1 = tmp;
    }
}

extern "C" void kernel_launch(void* const* d_in, const int* in_sizes, int n_in,
                              void* d_out, int out_size) {
    const float* users_feature   = (const float*)d_in[0];
    const float* items_feature   = (const float*)d_in[1];
    const float* bundles_feature = (const float*)d_in[2];
    const float* ui_vals = (const float*)d_in[3];
    const float* bi_vals = (const float*)d_in[4];
    const float* ub_vals = (const float*)d_in[5];
    const int* ui_rows = (const int*)d_in[6];
    const int* ui_cols = (const int*)d_in[7];
    const int* bi_rows = (const int*)d_in[8];
    const int* bi_cols = (const int*)d_in[9];
    const int* ub_rows = (const int*)d_in[10];
    const int* ub_cols = (const int*)d_in[11];

    int U  = in_sizes[0] / D;
    int NI = in_sizes[1] / D;
    int NB = in_sizes[2] / D;
    int nnz_ui = in_sizes[3];
    int nnz_bi = in_sizes[4];
    int nnz_ub = in_sizes[5];

    float* out = (float*)d_out;

    float *f0, *f1;
    cudaGetSymbolAddress((void**)&f0, g_f0);
    cudaGetSymbolAddress((void**)&f1, g_f1);

    // Output layout: [UI_u(U), UB_u(U), BI_b(NB), UB_b(NB), UI_i(NI), BI_i(NI)]
    float* o_ui_u = out;
    float* o_ub_u = out + (size_t)U * D;
    float* o_bi_b = out + (size_t)2 * U * D;
    float* o_ub_b = out + ((size_t)2 * U + NB) * D;
    float* o_ui_i = out + ((size_t)2 * U + 2 * NB) * D;
    float* o_bi_i = out + ((size_t)2 * U + 2 * NB + NI) * D;

    // UI: A=users (U), B=items (NI)
    run_prop(ui_rows, ui_cols, ui_vals, nnz_ui,
             users_feature, items_feature, U, NI, o_ui_u, o_ui_i, f0, f1);
    // BI: A=bundles (NB), B=items (NI)
    run_prop(bi_rows, bi_cols, bi_vals, nnz_bi,
             bundles_feature, items_feature, NB, NI, o_bi_b, o_bi_i, f0, f1);
    // UB: A=users (U), B=bundles (NB)
    run_prop(ub_rows, ub_cols, ub_vals, nnz_ub,
             users_feature, bundles_feature, U, NB, o_ub_u, o_ub_b, f0, f1);
}

// round 2
// speedup vs baseline: 1.3223x; 1.3223x over previous
#include <cuda_runtime.h>
#include <cstdint>

#define D 64
#define MAXN 150001
#define MAXNNZ 2000000
#define SCAN_B 256
#define MAXBLKS ((MAXN + SCAN_B - 1) / SCAN_B)   // <= 587

// ---- scratch (__device__ globals; no allocation allowed) ----
__device__ __align__(16) float g_f0[(size_t)MAXN * D];
__device__ __align__(16) float g_f1[(size_t)MAXN * D];
__device__ __align__(16) float2 g_edges[MAXNNZ];   // {col_bits, val}, bucketed by row
__device__ int g_counts[MAXN];
__device__ int g_offs[MAXN + 1];
__device__ int g_cursor[MAXN];
__device__ int g_part[MAXN];
__device__ int g_bsums[1024];

// ---- init: f0 = concat(A,B); out = feat/3 (layer-0 term) ----
__global__ void init_kernel(const float* __restrict__ A, const float* __restrict__ B,
                            int nA, int n, float* __restrict__ f0,
                            float* __restrict__ outA, float* __restrict__ outB) {
    int idx = blockIdx.x * blockDim.x + threadIdx.x;   // one float4 per thread
    int total = n * (D / 4);
    if (idx >= total) return;
    int row = idx >> 4;
    int c = (idx & 15) * 4;
    const float* src = (row < nA) ? (A + (size_t)row * D) : (B + (size_t)(row - nA) * D);
    float4 v = *(const float4*)(src + c);
    *(float4*)(f0 + (size_t)row * D + c) = v;
    float* dst = (row < nA) ? (outA + (size_t)row * D) : (outB + (size_t)(row - nA) * D);
    const float k = 1.0f / 3.0f;
    *(float4*)(dst + c) = make_float4(v.x * k, v.y * k, v.z * k, v.w * k);
}

// ---- CSR build ----
__global__ void hist_kernel(const int* __restrict__ rows, int nnz, int* __restrict__ counts) {
    int e = blockIdx.x * blockDim.x + threadIdx.x;
    if (e < nnz) atomicAdd(&counts[rows[e]], 1);
}

__global__ void scan1_kernel(const int* __restrict__ counts, int n,
                             int* __restrict__ part, int* __restrict__ bsums) {
    __shared__ int sm[SCAN_B];
    int i = blockIdx.x * SCAN_B + threadIdx.x;
    int v = (i < n) ? counts[i] : 0;
    sm[threadIdx.x] = v;
    __syncthreads();
    #pragma unroll
    for (int o = 1; o < SCAN_B; o <<= 1) {
        int t = (threadIdx.x >= o) ? sm[threadIdx.x - o] : 0;
        __syncthreads();
        sm[threadIdx.x] += t;
        __syncthreads();
    }
    if (i < n) part[i] = sm[threadIdx.x];
    if (threadIdx.x == SCAN_B - 1) bsums[blockIdx.x] = sm[SCAN_B - 1];
}

__global__ void scan2_kernel(int* __restrict__ bsums, int nb) {
    __shared__ int sm[1024];
    int t = threadIdx.x;
    int v = (t < nb) ? bsums[t] : 0;
    sm[t] = v;
    __syncthreads();
    #pragma unroll
    for (int o = 1; o < 1024; o <<= 1) {
        int u = (t >= o) ? sm[t - o] : 0;
        __syncthreads();
        sm[t] += u;
        __syncthreads();
    }
    if (t < nb) bsums[t] = sm[t] - v;   // exclusive
}

__global__ void scan3_kernel(const int* __restrict__ part, const int* __restrict__ bsums,
                             const int* __restrict__ counts, int n,
                             int* __restrict__ offs, int* __restrict__ cursor) {
    int i = blockIdx.x * SCAN_B + threadIdx.x;
    if (i >= n) return;
    int inc = part[i] + bsums[blockIdx.x];
    offs[i + 1] = inc;
    cursor[i] = inc - counts[i];
    if (i == 0) offs[0] = 0;
}

__global__ void bucket_kernel(const int* __restrict__ rows, const int* __restrict__ cols,
                              const float* __restrict__ vals, int nnz,
                              int* __restrict__ cursor, float2* __restrict__ edges) {
    int e = blockIdx.x * blockDim.x + threadIdx.x;
    if (e >= nnz) return;
    int r = rows[e];
    int pos = atomicAdd(&cursor[r], 1);
    edges[pos] = make_float2(__int_as_float(cols[e]), vals[e]);
}

// ---- fused gather-SpMM + L2-normalize + output accumulate ----
// One warp per row; each lane owns a float2 slice of D=64.
__global__ void spmm_norm_kernel(const float2* __restrict__ edges, const int* __restrict__ offs,
                                 const float* __restrict__ fin, float* __restrict__ fnext,
                                 int nA, int n, float* __restrict__ outA,
                                 float* __restrict__ outB, int write_next) {
    int row = (int)((blockIdx.x * blockDim.x + threadIdx.x) >> 5);
    int lane = threadIdx.x & 31;
    if (row >= n) return;
    int s = offs[row], e = offs[row + 1];
    float ax = 0.f, ay = 0.f;
    int i = s;
    // 2-way unrolled for MLP
    for (; i + 1 < e; i += 2) {
        float2 h0 = edges[i];
        float2 h1 = edges[i + 1];
        int c0 = __float_as_int(h0.x);
        int c1 = __float_as_int(h1.x);
        float2 x0 = *(const float2*)(fin + (size_t)c0 * D + lane * 2);
        float2 x1 = *(const float2*)(fin + (size_t)c1 * D + lane * 2);
        ax += h0.y * x0.x + h1.y * x1.x;
        ay += h0.y * x0.y + h1.y * x1.y;
    }
    if (i < e) {
        float2 h = edges[i];
        int c = __float_as_int(h.x);
        float2 x = *(const float2*)(fin + (size_t)c * D + lane * 2);
        ax += h.y * x.x;
        ay += h.y * x.y;
    }
    if (write_next)
        *(float2*)(fnext + (size_t)row * D + lane * 2) = make_float2(ax, ay);
    float ssum = ax * ax + ay * ay;
    #pragma unroll
    for (int o = 16; o; o >>= 1) ssum += __shfl_xor_sync(0xffffffffu, ssum, o);
    float scale = (1.0f / 3.0f) / fmaxf(sqrtf(ssum), 1e-12f);
    float* dst = (row < nA) ? (outA + (size_t)row * D) : (outB + (size_t)(row - nA) * D);
    float2* d2 = (float2*)dst + lane;
    float2 o2 = *d2;
    o2.x += ax * scale;
    o2.y += ay * scale;
    *d2 = o2;
}

static void run_prop(const int* rows, const int* cols, const float* vals, int nnz,
                     const float* A, const float* B, int nA, int nB,
                     float* outA, float* outB,
                     float* f0, float* f1, float2* edges,
                     int* counts, int* offs, int* cursor, int* part, int* bsums) {
    int n = nA + nB;
    int nb = (n + SCAN_B - 1) / SCAN_B;

    // init acc + f0
    init_kernel<<<(n * (D / 4) + 255) / 256, 256>>>(A, B, nA, n, f0, outA, outB);

    // CSR build (once, reused for both layers)
    cudaMemsetAsync(counts, 0, (size_t)n * sizeof(int), 0);
    hist_kernel<<<(nnz + 255) / 256, 256>>>(rows, nnz, counts);
    scan1_kernel<<<nb, SCAN_B>>>(counts, n, part, bsums);
    scan2_kernel<<<1, 1024>>>(bsums, nb);
    scan3_kernel<<<nb, SCAN_B>>>(part, bsums, counts, n, offs, cursor);
    bucket_kernel<<<(nnz + 255) / 256, 256>>>(rows, cols, vals, nnz, cursor, edges);

    // layer 1: write f1; layer 2: no next buffer needed
    int blocks = (n + 7) / 8;   // 8 warps/block
    spmm_norm_kernel<<<blocks, 256>>>(edges, offs, f0, f1, nA, n, outA, outB, 1);
    spmm_norm_kernel<<<blocks, 256>>>(edges, offs, f1, f0, nA, n, outA, outB, 0);
}

extern "C" void kernel_launch(void* const* d_in, const int* in_sizes, int n_in,
                              void* d_out, int out_size) {
    const float* users_feature   = (const float*)d_in[0];
    const float* items_feature   = (const float*)d_in[1];
    const float* bundles_feature = (const float*)d_in[2];
    const float* ui_vals = (const float*)d_in[3];
    const float* bi_vals = (const float*)d_in[4];
    const float* ub_vals = (const float*)d_in[5];
    const int* ui_rows = (const int*)d_in[6];
    const int* ui_cols = (const int*)d_in[7];
    const int* bi_rows = (const int*)d_in[8];
    const int* bi_cols = (const int*)d_in[9];
    const int* ub_rows = (const int*)d_in[10];
    const int* ub_cols = (const int*)d_in[11];

    int U  = in_sizes[0] / D;
    int NI = in_sizes[1] / D;
    int NB = in_sizes[2] / D;
    int nnz_ui = in_sizes[3];
    int nnz_bi = in_sizes[4];
    int nnz_ub = in_sizes[5];

    float* out = (float*)d_out;

    float *f0, *f1, *counts_f;
    float2* edges;
    int *counts, *offs, *cursor, *part, *bsums;
    cudaGetSymbolAddress((void**)&f0, g_f0);
    cudaGetSymbolAddress((void**)&f1, g_f1);
    cudaGetSymbolAddress((void**)&edges, g_edges);
    cudaGetSymbolAddress((void**)&counts, g_counts);
    cudaGetSymbolAddress((void**)&offs, g_offs);
    cudaGetSymbolAddress((void**)&cursor, g_cursor);
    cudaGetSymbolAddress((void**)&part, g_part);
    cudaGetSymbolAddress((void**)&bsums, g_bsums);
    (void)counts_f;

    // Output layout: [UI_u(U), UB_u(U), BI_b(NB), UB_b(NB), UI_i(NI), BI_i(NI)]
    float* o_ui_u = out;
    float* o_ub_u = out + (size_t)U * D;
    float* o_bi_b = out + (size_t)2 * U * D;
    float* o_ub_b = out + ((size_t)2 * U + NB) * D;
    float* o_ui_i = out + ((size_t)2 * U + 2 * NB) * D;
    float* o_bi_i = out + ((size_t)2 * U + 2 * NB + NI) * D;

    run_prop(ui_rows, ui_cols, ui_vals, nnz_ui, users_feature, items_feature,
             U, NI, o_ui_u, o_ui_i, f0, f1, edges, counts, offs, cursor, part, bsums);
    run_prop(bi_rows, bi_cols, bi_vals, nnz_bi, bundles_feature, items_feature,
             NB, NI, o_bi_b, o_bi_i, f0, f1, edges, counts, offs, cursor, part, bsums);
    run_prop(ub_rows, ub_cols, ub_vals, nnz_ub, users_feature, bundles_feature,
             U, NB, o_ub_u, o_ub_b, f0, f1, edges, counts, offs, cursor, part, bsums);
}